// round 3
// baseline (speedup 1.0000x reference)
#include <cuda_runtime.h>
#include <cstdint>

// Problem constants
#define Tn   1024
#define Bn   64
#define Dn   32
#define Hn   512
#define KK   544            // H + D concatenated K dimension
#define HB   (Hn * Bn)
#define NCTA 128
#define NTHR 256

// Scratch (device globals: allocation-free per harness rules)
__device__ float    g_xT[(size_t)Tn * Dn * Bn];          // [t][d][b]
__device__ float    g_hist[(size_t)(Tn + 1) * HB];       // [t][h][b]
__device__ unsigned g_flags[NCTA];                       // per-CTA step counter

// SMEM layout (floats):
//   sm_h    [KK*64]      k-major activations (h | x)
//   sm_w    [KK*16] ull  weights duplicated as (w,w) f32x2
//   sm_g    [16*64]      gate exchange / conv reduce scratch
//   sm_bias [16]
#define SMEM_FLOATS (KK*Bn + KK*32 + 16*Bn + 16)
#define SMEM_BYTES  (SMEM_FLOATS * 4)

// ---------------------------------------------------------------------------
__global__ void lstm_prep_kernel(const float* __restrict__ x) {
    long long idx = (long long)blockIdx.x * blockDim.x + threadIdx.x;
    if (idx < NCTA) g_flags[idx] = 0u;
    if (idx < HB)   g_hist[idx] = 0.f;
    const long long total = (long long)Bn * Dn * Tn;
    if (idx < total) {
        int t = (int)(idx % Tn);
        int d = (int)((idx / Tn) % Dn);
        int b = (int)(idx / ((long long)Tn * Dn));
        g_xT[(size_t)t * Dn * Bn + d * Bn + b] = x[idx];
    }
}

// ---------------------------------------------------------------------------
// helpers
// ---------------------------------------------------------------------------
__device__ __forceinline__ void cp16(uint32_t saddr, const void* gptr) {
    asm volatile("cp.async.cg.shared.global [%0], [%1], 16;"
                 :: "r"(saddr), "l"(gptr));
}
__device__ __forceinline__ void cp_commit() {
    asm volatile("cp.async.commit_group;");
}
template <int N>
__device__ __forceinline__ void cp_wait() {
    asm volatile("cp.async.wait_group %0;" :: "n"(N));
}

// All-CTA step barrier: wait until every CTA's flag >= target.
__device__ __forceinline__ void wait_flags(unsigned target, int tid) {
    if (tid < 32) {
        const uint4* fp = (const uint4*)g_flags + tid;  // 32 lanes x 4 flags
        for (;;) {
            uint4 v;
            asm volatile("ld.volatile.global.v4.u32 {%0,%1,%2,%3}, [%4];"
                         : "=r"(v.x), "=r"(v.y), "=r"(v.z), "=r"(v.w)
                         : "l"(fp));
            bool ok = (v.x >= target) & (v.y >= target) &
                      (v.z >= target) & (v.w >= target);
            if (__all_sync(0xffffffffu, ok)) break;
            __nanosleep(32);
        }
        asm volatile("fence.acq_rel.gpu;" ::: "memory");
    }
    __syncthreads();
}

__device__ __forceinline__ float fsigmoid(float x) {
    return 1.f / (1.f + __expf(-x));
}
__device__ __forceinline__ float ftanh(float x) {
    return 1.f - 2.f / (__expf(2.f * x) + 1.f);
}

// ---------------------------------------------------------------------------
// Persistent LSTM recurrence + fused conv tail
// ---------------------------------------------------------------------------
extern __shared__ float smem[];

__global__ void __launch_bounds__(NTHR, 1) lstm_main_kernel(
    const float* __restrict__ W_ih,   // [4H, D]
    const float* __restrict__ W_hh,   // [4H, H]
    const float* __restrict__ b_ih,   // [4H]
    const float* __restrict__ b_hh,   // [4H]
    const float* __restrict__ cw,     // [H] conv weight
    const float* __restrict__ cb,     // [1]
    float* __restrict__ out)          // (B, 1, T)
{
    float* sm_h = smem;                                       // KK*64 floats
    unsigned long long* sm_w = (unsigned long long*)(smem + KK * Bn); // KK*16 ull
    float* sm_g    = smem + KK * Bn + KK * 32;                // 16*64 floats
    float* sm_bias = sm_g + 16 * Bn;                          // 16 floats

    const int tid = threadIdx.x;
    const int cta = blockIdx.x;

    // ---- one-time: weights (dup f32x2) + bias ----
    for (int i = tid; i < 16 * KK; i += NTHR) {
        int k = i >> 4, n = i & 15;
        int row = (n >> 2) * Hn + cta * 4 + (n & 3);
        float w = (k < Hn) ? W_hh[(size_t)row * Hn + k]
                           : W_ih[(size_t)row * Dn + (k - Hn)];
        unsigned u = __float_as_uint(w);
        sm_w[(size_t)k * 16 + n] = ((unsigned long long)u << 32) | u;
    }
    if (tid < 16) {
        int row = (tid >> 2) * Hn + cta * 4 + (tid & 3);
        sm_bias[tid] = b_ih[row] + b_hh[row];
    }
    __syncthreads();

    // GEMM thread mapping: 2n x 2b tile
    const int lane = tid & 31, wd = tid >> 5;
    const int n2 = (wd & 1) * 4 + (lane & 3);    // n-pair   0..7
    const int bp = (wd >> 1) * 8 + (lane >> 2);  // b-pair   0..31
    const ulonglong2*       wp = (const ulonglong2*)sm_w + n2;          // +k*8
    const unsigned long long* hp = (const unsigned long long*)sm_h + bp; // +k*32

    // epilogue mapping
    const int ehi = tid >> 6;   // 0..3  (h index within CTA's 4 rows)
    const int eb  = tid & 63;   // batch
    float c_reg = 0.f;

    const uint32_t sbase = (uint32_t)__cvta_generic_to_shared(sm_h);

    for (int t = 0; t < Tn; ++t) {
        wait_flags((unsigned)t, tid);

        const float4* gs = (const float4*)(g_hist + (size_t)t * HB);
        const float4* gx = (const float4*)(g_xT + (size_t)t * Dn * Bn);

        // issue chunk0, chunk1 (each 128 k-rows = 2048 float4)
        #pragma unroll
        for (int i = 0; i < 8; ++i) {
            int idx = tid + i * NTHR;
            cp16(sbase + (uint32_t)idx * 16u, gs + idx);
        }
        cp_commit();
        #pragma unroll
        for (int i = 0; i < 8; ++i) {
            int idx = 2048 + tid + i * NTHR;
            cp16(sbase + (uint32_t)idx * 16u, gs + idx);
        }
        cp_commit();

        unsigned long long acc0 = 0ull, acc1 = 0ull;

        // ---- chunk 0 (stage chunk2 behind it) ----
        #pragma unroll
        for (int i = 0; i < 8; ++i) {
            int idx = 4096 + tid + i * NTHR;
            cp16(sbase + (uint32_t)idx * 16u, gs + idx);
        }
        cp_commit();
        cp_wait<2>(); __syncthreads();
        #pragma unroll 8
        for (int k = 0; k < 128; ++k) {
            ulonglong2 w2 = wp[(size_t)k * 8];
            unsigned long long h2 = hp[(size_t)k * 32];
            asm("fma.rn.f32x2 %0, %1, %2, %0;" : "+l"(acc0) : "l"(w2.x), "l"(h2));
            asm("fma.rn.f32x2 %0, %1, %2, %0;" : "+l"(acc1) : "l"(w2.y), "l"(h2));
        }
        // ---- chunk 1 (stage chunk3) ----
        #pragma unroll
        for (int i = 0; i < 8; ++i) {
            int idx = 6144 + tid + i * NTHR;
            cp16(sbase + (uint32_t)idx * 16u, gs + idx);
        }
        cp_commit();
        cp_wait<2>(); __syncthreads();
        #pragma unroll 8
        for (int k = 128; k < 256; ++k) {
            ulonglong2 w2 = wp[(size_t)k * 8];
            unsigned long long h2 = hp[(size_t)k * 32];
            asm("fma.rn.f32x2 %0, %1, %2, %0;" : "+l"(acc0) : "l"(w2.x), "l"(h2));
            asm("fma.rn.f32x2 %0, %1, %2, %0;" : "+l"(acc1) : "l"(w2.y), "l"(h2));
        }
        // ---- chunk 2 (stage x chunk) ----
        #pragma unroll
        for (int i = 0; i < 2; ++i) {
            int idx = tid + i * NTHR;
            cp16(sbase + (uint32_t)(8192 + idx) * 16u, gx + idx);
        }
        cp_commit();
        cp_wait<2>(); __syncthreads();
        #pragma unroll 8
        for (int k = 256; k < 384; ++k) {
            ulonglong2 w2 = wp[(size_t)k * 8];
            unsigned long long h2 = hp[(size_t)k * 32];
            asm("fma.rn.f32x2 %0, %1, %2, %0;" : "+l"(acc0) : "l"(w2.x), "l"(h2));
            asm("fma.rn.f32x2 %0, %1, %2, %0;" : "+l"(acc1) : "l"(w2.y), "l"(h2));
        }
        // ---- chunk 3 ----
        cp_wait<1>(); __syncthreads();
        #pragma unroll 8
        for (int k = 384; k < 512; ++k) {
            ulonglong2 w2 = wp[(size_t)k * 8];
            unsigned long long h2 = hp[(size_t)k * 32];
            asm("fma.rn.f32x2 %0, %1, %2, %0;" : "+l"(acc0) : "l"(w2.x), "l"(h2));
            asm("fma.rn.f32x2 %0, %1, %2, %0;" : "+l"(acc1) : "l"(w2.y), "l"(h2));
        }
        // ---- chunk 4 (x part) ----
        cp_wait<0>(); __syncthreads();
        #pragma unroll 8
        for (int k = 512; k < KK; ++k) {
            ulonglong2 w2 = wp[(size_t)k * 8];
            unsigned long long h2 = hp[(size_t)k * 32];
            asm("fma.rn.f32x2 %0, %1, %2, %0;" : "+l"(acc0) : "l"(w2.x), "l"(h2));
            asm("fma.rn.f32x2 %0, %1, %2, %0;" : "+l"(acc1) : "l"(w2.y), "l"(h2));
        }

        // ---- exchange gates via SMEM ----
        {
            float2* gp = (float2*)sm_g;
            gp[(2 * n2 + 0) * 32 + bp] = *(float2*)&acc0;
            gp[(2 * n2 + 1) * 32 + bp] = *(float2*)&acc1;
        }
        __syncthreads();

        // ---- LSTM cell epilogue ----
        {
            float xi = sm_g[(0  + ehi) * Bn + eb] + sm_bias[0  + ehi];
            float xf = sm_g[(4  + ehi) * Bn + eb] + sm_bias[4  + ehi];
            float xg = sm_g[(8  + ehi) * Bn + eb] + sm_bias[8  + ehi];
            float xo = sm_g[(12 + ehi) * Bn + eb] + sm_bias[12 + ehi];
            float ii = fsigmoid(xi);
            float ff = fsigmoid(xf);
            float gg = ftanh(xg);
            float oo = fsigmoid(xo);
            c_reg = ff * c_reg + ii * gg;
            float h = oo * ftanh(c_reg);
            g_hist[(size_t)(t + 1) * HB + (cta * 4 + ehi) * Bn + eb] = h;
        }
        __syncthreads();

        // ---- publish: parallel per-CTA flag (release) ----
        if (tid == 0) {
            asm volatile("fence.acq_rel.gpu;" ::: "memory");
            asm volatile("st.volatile.global.u32 [%0], %1;"
                         :: "l"(&g_flags[cta]), "r"((unsigned)(t + 1)) : "memory");
        }
    }

    // ================= fused conv tail =================
    wait_flags((unsigned)Tn, tid);

    float* sm_cw = sm_h;  // reuse
    for (int i = tid; i < Hn; i += NTHR) sm_cw[i] = cw[i];
    const float cbv = cb[0];
    __syncthreads();

    const int q = tid >> 6;
    for (int tt = 0; tt < Tn / NCTA; ++tt) {
        int t = cta * (Tn / NCTA) + tt;
        const float* hp2 = g_hist + (size_t)(t + 1) * HB + eb;
        float acc = 0.f;
        #pragma unroll 8
        for (int h = q * 128; h < q * 128 + 128; ++h)
            acc += __ldcg(hp2 + (size_t)h * Bn) * sm_cw[h];
        sm_g[tid] = acc;
        __syncthreads();
        if (q == 0)
            out[(size_t)eb * Tn + t] =
                sm_g[eb] + sm_g[eb + 64] + sm_g[eb + 128] + sm_g[eb + 192] + cbv;
        __syncthreads();
    }
}

// ---------------------------------------------------------------------------
extern "C" void kernel_launch(void* const* d_in, const int* in_sizes, int n_in,
                              void* d_out, int out_size)
{
    const float* x    = (const float*)d_in[0];  // (B, D, T)
    const float* W_ih = (const float*)d_in[1];  // (4H, D)
    const float* W_hh = (const float*)d_in[2];  // (4H, H)
    const float* b_ih = (const float*)d_in[3];  // (4H,)
    const float* b_hh = (const float*)d_in[4];  // (4H,)
    const float* cw   = (const float*)d_in[5];  // (1, H, 1)
    const float* cb   = (const float*)d_in[6];  // (1,)
    float* out = (float*)d_out;                 // (B, 1, T)

    cudaFuncSetAttribute(lstm_main_kernel,
                         cudaFuncAttributeMaxDynamicSharedMemorySize, SMEM_BYTES);

    lstm_prep_kernel<<<(Bn * Dn * Tn + 255) / 256, 256>>>(x);
    lstm_main_kernel<<<NCTA, NTHR, SMEM_BYTES>>>(W_ih, W_hh, b_ih, b_hh,
                                                 cw, cb, out);
}

// round 4
// speedup vs baseline: 1.2693x; 1.2693x over previous
#include <cuda_runtime.h>
#include <cstdint>

// Problem constants
#define Tn   1024
#define Bn   64
#define Dn   32
#define Hn   512
#define KK   544            // H + D concatenated K dimension
#define HB   (Hn * Bn)
#define NCTA 128
#define NTHR 256

// Scratch (device globals: allocation-free per harness rules)
__device__ float    g_xT[(size_t)Tn * Dn * Bn];          // [t][d][b]
__device__ float    g_hist[(size_t)(Tn + 1) * HB];       // [t][h][b]
__device__ unsigned g_flags[NCTA];                       // per-CTA step counter

// SMEM layout (floats):
//   sm_h    [KK*64]        k-major activations (h | x)           139264 B
//   sm_w    [KK*16] (ull)  weights duplicated (w,w) as f32x2      69632 B
//   sm_r    [8*256]        k-split reduction scratch (SoA)         8192 B
//   sm_g    [16*64]        gate exchange                           4096 B
//   sm_bias [16]
#define SMEM_FLOATS (KK*Bn + KK*32 + 8*NTHR + 16*Bn + 16)
#define SMEM_BYTES  (SMEM_FLOATS * 4)

// ---------------------------------------------------------------------------
__global__ void lstm_prep_kernel(const float* __restrict__ x) {
    long long idx = (long long)blockIdx.x * blockDim.x + threadIdx.x;
    if (idx < NCTA) g_flags[idx] = 0u;
    if (idx < HB)   g_hist[idx] = 0.f;
    const long long total = (long long)Bn * Dn * Tn;
    if (idx < total) {
        int t = (int)(idx % Tn);
        int d = (int)((idx / Tn) % Dn);
        int b = (int)(idx / ((long long)Tn * Dn));
        g_xT[(size_t)t * Dn * Bn + d * Bn + b] = x[idx];
    }
}

// ---------------------------------------------------------------------------
// All-CTA step barrier: wait until every CTA's flag >= target.
__device__ __forceinline__ void wait_flags(unsigned target, int tid) {
    if (tid < 32) {
        const uint4* fp = (const uint4*)g_flags + tid;   // 32 lanes x 4 flags
        for (;;) {
            uint4 v;
            asm volatile("ld.volatile.global.v4.u32 {%0,%1,%2,%3}, [%4];"
                         : "=r"(v.x), "=r"(v.y), "=r"(v.z), "=r"(v.w)
                         : "l"(fp));
            bool ok = (v.x >= target) & (v.y >= target) &
                      (v.z >= target) & (v.w >= target);
            if (__all_sync(0xffffffffu, ok)) break;
            __nanosleep(32);
        }
        asm volatile("fence.acq_rel.gpu;" ::: "memory");
    }
    __syncthreads();
}

__device__ __forceinline__ float fsigmoid(float x) {
    return 1.f / (1.f + __expf(-x));
}
__device__ __forceinline__ float ftanh_(float x) {
    return 1.f - 2.f / (__expf(2.f * x) + 1.f);
}

// ---------------------------------------------------------------------------
extern __shared__ float smem[];

__global__ void __launch_bounds__(NTHR, 1) lstm_main_kernel(
    const float* __restrict__ W_ih,   // [4H, D]
    const float* __restrict__ W_hh,   // [4H, H]
    const float* __restrict__ b_ih,   // [4H]
    const float* __restrict__ b_hh)   // [4H]
{
    float* sm_h = smem;                                            // KK*64
    unsigned long long* sm_w = (unsigned long long*)(smem + KK * Bn);
    float* sm_r    = smem + KK * Bn + KK * 32;                     // 8*256
    float* sm_g    = sm_r + 8 * NTHR;                              // 16*64
    float* sm_bias = sm_g + 16 * Bn;                               // 16

    const int tid = threadIdx.x;
    const int cta = blockIdx.x;

    // ---- one-time: weights (dup f32x2) + bias ----
    for (int i = tid; i < 16 * KK; i += NTHR) {
        int k = i >> 4, n = i & 15;
        int row = (n >> 2) * Hn + cta * 4 + (n & 3);
        float w = (k < Hn) ? W_hh[(size_t)row * Hn + k]
                           : W_ih[(size_t)row * Dn + (k - Hn)];
        unsigned u = __float_as_uint(w);
        sm_w[(size_t)k * 16 + n] = ((unsigned long long)u << 32) | u;
    }
    if (tid < 16) {
        int row = (tid >> 2) * Hn + cta * 4 + (tid & 3);
        sm_bias[tid] = b_ih[row] + b_hh[row];
    }
    __syncthreads();

    // GEMM thread mapping: 2n x 4b tile, k split across warp halves.
    //   warp w (0..7): kh = w>>2, wb = w&3
    //   lane: n2 = lane&7 (n-pair), bq = wb*4 + (lane>>3) (b-quad)
    const int lane = tid & 31, wrp = tid >> 5;
    const int kh = wrp >> 2;                 // 0 or 1
    const int n2 = lane & 7;                 // n-pair 0..7
    const int bq = (wrp & 3) * 4 + (lane >> 3); // b-quad 0..15
    const int k0 = kh * (KK / 2);            // 0 or 272
    const ulonglong2* wp = (const ulonglong2*)sm_w + n2;  // +k*8
    const ulonglong2* hp = (const ulonglong2*)sm_h + bq;  // +k*16

    // epilogue mapping
    const int ehi = tid >> 6;    // 0..3
    const int eb  = tid & 63;    // batch
    float c_reg = 0.f;

    for (int t = 0; t < Tn; ++t) {
        wait_flags((unsigned)t, tid);

        // ---- stage h_t (k-major) + x_t into SMEM: one burst ----
        {
            const float4* srch = (const float4*)(g_hist + (size_t)t * HB);
            const float4* srcx = (const float4*)(g_xT + (size_t)t * Dn * Bn);
            float4* dst = (float4*)sm_h;
            #pragma unroll
            for (int i = 0; i < 32; ++i)                // 8192 float4 of h
                dst[tid + i * NTHR] = __ldcg(srch + tid + i * NTHR);
            #pragma unroll
            for (int i = 0; i < 2; ++i)                 // 512 float4 of x
                dst[8192 + tid + i * NTHR] = __ldcg(srcx + tid + i * NTHR);
        }
        __syncthreads();

        // ---- GEMM half-K: acc[2n][4b] ----
        unsigned long long a00 = 0, a01 = 0, a10 = 0, a11 = 0;
        #pragma unroll 8
        for (int k = k0; k < k0 + KK / 2; ++k) {
            ulonglong2 w2 = wp[(size_t)k * 8];
            ulonglong2 h2 = hp[(size_t)k * 16];
            asm("fma.rn.f32x2 %0, %1, %2, %0;" : "+l"(a00) : "l"(w2.x), "l"(h2.x));
            asm("fma.rn.f32x2 %0, %1, %2, %0;" : "+l"(a01) : "l"(w2.x), "l"(h2.y));
            asm("fma.rn.f32x2 %0, %1, %2, %0;" : "+l"(a10) : "l"(w2.y), "l"(h2.x));
            asm("fma.rn.f32x2 %0, %1, %2, %0;" : "+l"(a11) : "l"(w2.y), "l"(h2.y));
        }

        // ---- k-split reduction: kh=1 threads publish, kh=0 threads add ----
        {
            int slot = (wrp & 3) * 32 + lane;   // 0..127 within k-half
            if (kh == 1) {
                float2 p;
                p = *(float2*)&a00; sm_r[0*NTHR + slot] = p.x; sm_r[1*NTHR + slot] = p.y;
                p = *(float2*)&a01; sm_r[2*NTHR + slot] = p.x; sm_r[3*NTHR + slot] = p.y;
                p = *(float2*)&a10; sm_r[4*NTHR + slot] = p.x; sm_r[5*NTHR + slot] = p.y;
                p = *(float2*)&a11; sm_r[6*NTHR + slot] = p.x; sm_r[7*NTHR + slot] = p.y;
            }
        }
        __syncthreads();
        if (kh == 0) {
            int slot = (wrp & 3) * 32 + lane;
            float2 q;
            q = *(float2*)&a00; q.x += sm_r[0*NTHR+slot]; q.y += sm_r[1*NTHR+slot];
            sm_g[(2*n2+0)*Bn + bq*4 + 0] = q.x;  sm_g[(2*n2+0)*Bn + bq*4 + 1] = q.y;
            q = *(float2*)&a01; q.x += sm_r[2*NTHR+slot]; q.y += sm_r[3*NTHR+slot];
            sm_g[(2*n2+0)*Bn + bq*4 + 2] = q.x;  sm_g[(2*n2+0)*Bn + bq*4 + 3] = q.y;
            q = *(float2*)&a10; q.x += sm_r[4*NTHR+slot]; q.y += sm_r[5*NTHR+slot];
            sm_g[(2*n2+1)*Bn + bq*4 + 0] = q.x;  sm_g[(2*n2+1)*Bn + bq*4 + 1] = q.y;
            q = *(float2*)&a11; q.x += sm_r[6*NTHR+slot]; q.y += sm_r[7*NTHR+slot];
            sm_g[(2*n2+1)*Bn + bq*4 + 2] = q.x;  sm_g[(2*n2+1)*Bn + bq*4 + 3] = q.y;
        }
        __syncthreads();

        // ---- LSTM cell epilogue ----
        {
            float xi = sm_g[(0  + ehi) * Bn + eb] + sm_bias[0  + ehi];
            float xf = sm_g[(4  + ehi) * Bn + eb] + sm_bias[4  + ehi];
            float xg = sm_g[(8  + ehi) * Bn + eb] + sm_bias[8  + ehi];
            float xo = sm_g[(12 + ehi) * Bn + eb] + sm_bias[12 + ehi];
            float ii = fsigmoid(xi);
            float ff = fsigmoid(xf);
            float gg = ftanh_(xg);
            float oo = fsigmoid(xo);
            c_reg = ff * c_reg + ii * gg;
            float h = oo * ftanh_(c_reg);
            g_hist[(size_t)(t + 1) * HB + (cta * 4 + ehi) * Bn + eb] = h;
        }
        __syncthreads();

        // ---- publish per-CTA flag (release) ----
        if (tid == 0) {
            asm volatile("fence.acq_rel.gpu;" ::: "memory");
            asm volatile("st.volatile.global.u32 [%0], %1;"
                         :: "l"(&g_flags[cta]), "r"((unsigned)(t + 1)) : "memory");
        }
    }
}

// ---------------------------------------------------------------------------
// Conv1d(H,1,kernel=1): pred[b][t] = sum_h h[t+1][h][b]*cw[h] + cb
// ---------------------------------------------------------------------------
__global__ void lstm_conv_kernel(const float* __restrict__ cw,
                                 const float* __restrict__ cb,
                                 float* __restrict__ out)
{
    int t = blockIdx.x;
    int b = threadIdx.x;
    const float* hp = g_hist + (size_t)(t + 1) * HB + b;
    float acc = 0.f;
    #pragma unroll 8
    for (int h = 0; h < Hn; ++h)
        acc += __ldcg(hp + (size_t)h * Bn) * __ldg(cw + h);
    out[(size_t)b * Tn + t] = acc + cb[0];
}

// ---------------------------------------------------------------------------
extern "C" void kernel_launch(void* const* d_in, const int* in_sizes, int n_in,
                              void* d_out, int out_size)
{
    const float* x    = (const float*)d_in[0];  // (B, D, T)
    const float* W_ih = (const float*)d_in[1];  // (4H, D)
    const float* W_hh = (const float*)d_in[2];  // (4H, H)
    const float* b_ih = (const float*)d_in[3];  // (4H,)
    const float* b_hh = (const float*)d_in[4];  // (4H,)
    const float* cw   = (const float*)d_in[5];  // (1, H, 1)
    const float* cb   = (const float*)d_in[6];  // (1,)
    float* out = (float*)d_out;                 // (B, 1, T)

    cudaFuncSetAttribute(lstm_main_kernel,
                         cudaFuncAttributeMaxDynamicSharedMemorySize, SMEM_BYTES);

    lstm_prep_kernel<<<(Bn * Dn * Tn + 255) / 256, 256>>>(x);
    lstm_main_kernel<<<NCTA, NTHR, SMEM_BYTES>>>(W_ih, W_hh, b_ih, b_hh);
    lstm_conv_kernel<<<Tn, Bn>>>(cw, cb, out);
}

// round 6
// speedup vs baseline: 1.6050x; 1.2644x over previous
#include <cuda_runtime.h>
#include <cstdint>

// Problem constants
#define Tn   1024
#define Bn   64
#define Dn   32
#define Hn   512
#define NG   4          // independent batch groups
#define GC   32         // CTAs per group
#define BG   16         // batches per group
#define NCTA 128
#define NTHR 256

// Device-global scratch (no allocations allowed)
__device__ float    g_xT  [(size_t)Tn * Dn * Bn];                 // [t][d][b]
__device__ float    g_xp  [(size_t)Tn * NG * GC * 64 * BG];       // [t][g][c][r][bl]
__device__ float    g_hist[(size_t)(Tn + 1) * NG * Hn * BG];      // [t][g][h][bl]
__device__ unsigned g_flags[NCTA];

// SMEM layout (floats)
#define RPAD  68
#define SM_W  (512 * 64)        // W_hh slice, k-major [k][r]          131072 B
#define SM_HD (512 * 32)        // h duplicated [k][(b,b) x16]          65536 B
#define SM_R  (4 * 16 * RPAD)   // k-split partials [kq][b][r pad]      17408 B
#define SM_G  (16 * RPAD)       // reduced gates [b][r pad]              4352 B
#define SMEM_FLOATS (SM_W + SM_HD + SM_R + SM_G)
#define SMEM_BYTES  (SMEM_FLOATS * 4)

// ---------------------------------------------------------------------------
// Prep: transpose x (B,D,T)->(T,D,B), zero hist[0], zero flags
// ---------------------------------------------------------------------------
__global__ void lstm_prep_kernel(const float* __restrict__ x) {
    long long idx = (long long)blockIdx.x * blockDim.x + threadIdx.x;
    if (idx < NCTA) g_flags[idx] = 0u;
    if (idx < NG * Hn * BG) g_hist[idx] = 0.f;
    const long long total = (long long)Bn * Dn * Tn;
    if (idx < total) {
        int t = (int)(idx % Tn);
        int d = (int)((idx / Tn) % Dn);
        int b = (int)(idx / ((long long)Tn * Dn));
        g_xT[(size_t)t * Dn * Bn + d * Bn + b] = x[idx];
    }
}

// ---------------------------------------------------------------------------
// xproj: xp[t][g][c][r][bl] = sum_d x[t][d][b]*W_ih[n][d] + b_ih[n] + b_hh[n]
//   n = (r>>4)*Hn + c*16 + (r&15),  b = g*16 + bl
// ---------------------------------------------------------------------------
__global__ void __launch_bounds__(NTHR) lstm_xproj_kernel(
    const float* __restrict__ W_ih, const float* __restrict__ b_ih,
    const float* __restrict__ b_hh)
{
    __shared__ float sx[Dn * Bn];    // [d][64b]
    __shared__ float swT[Dn * 64];   // [d][64r]
    __shared__ float sb[64];
    const int t = blockIdx.x, c = blockIdx.y, tid = threadIdx.x;

    for (int i = tid; i < Dn * Bn; i += NTHR)
        sx[i] = g_xT[(size_t)t * Dn * Bn + i];
    for (int i = tid; i < 2048; i += NTHR) {
        int r = i >> 5, d = i & 31;
        int n = (r >> 4) * Hn + c * 16 + (r & 15);
        swT[d * 64 + r] = W_ih[(size_t)n * Dn + d];
    }
    if (tid < 64) {
        int n = (tid >> 4) * Hn + c * 16 + (tid & 15);
        sb[tid] = b_ih[n] + b_hh[n];
    }
    __syncthreads();

    const int g = tid & 3, r = tid >> 2;
    float a[16];
    float bb = sb[r];
    #pragma unroll
    for (int j = 0; j < 16; ++j) a[j] = bb;

    #pragma unroll 4
    for (int d = 0; d < Dn; ++d) {
        float w = swT[d * 64 + r];
        const float4* xr = (const float4*)(sx + d * Bn + g * 16);
        float4 x0 = xr[0], x1 = xr[1], x2 = xr[2], x3 = xr[3];
        a[0]  += w * x0.x; a[1]  += w * x0.y; a[2]  += w * x0.z; a[3]  += w * x0.w;
        a[4]  += w * x1.x; a[5]  += w * x1.y; a[6]  += w * x1.z; a[7]  += w * x1.w;
        a[8]  += w * x2.x; a[9]  += w * x2.y; a[10] += w * x2.z; a[11] += w * x2.w;
        a[12] += w * x3.x; a[13] += w * x3.y; a[14] += w * x3.z; a[15] += w * x3.w;
    }
    float* dst = g_xp + (((size_t)t * NG + g) * GC + c) * 1024 + r * 16;
    ((float4*)dst)[0] = make_float4(a[0],  a[1],  a[2],  a[3]);
    ((float4*)dst)[1] = make_float4(a[4],  a[5],  a[6],  a[7]);
    ((float4*)dst)[2] = make_float4(a[8],  a[9],  a[10], a[11]);
    ((float4*)dst)[3] = make_float4(a[12], a[13], a[14], a[15]);
}

// ---------------------------------------------------------------------------
// Group barrier: wait until all 32 flags of this group are >= target.
// ---------------------------------------------------------------------------
__device__ __forceinline__ void group_wait(const unsigned* flags,
                                           unsigned target, int tid) {
    if (tid < 8) {
        const uint4* fp = (const uint4*)flags + tid;   // 8 lanes x 4 flags
        for (;;) {
            uint4 v;
            asm volatile("ld.volatile.global.v4.u32 {%0,%1,%2,%3}, [%4];"
                         : "=r"(v.x), "=r"(v.y), "=r"(v.z), "=r"(v.w)
                         : "l"(fp));
            bool ok = (v.x >= target) & (v.y >= target) &
                      (v.z >= target) & (v.w >= target);
            if (__all_sync(0xffu, ok)) break;
            __nanosleep(40);
        }
        asm volatile("fence.acq_rel.gpu;" ::: "memory");
    }
    __syncthreads();
}

__device__ __forceinline__ float fsigmoid(float x) {
    return 1.f / (1.f + __expf(-x));
}
__device__ __forceinline__ float ftanh_(float x) {
    return 1.f - 2.f / (__expf(2.f * x) + 1.f);
}

// ---------------------------------------------------------------------------
// Persistent LSTM recurrence: 4 independent groups of 32 CTAs
// ---------------------------------------------------------------------------
extern __shared__ float smem[];

__global__ void __launch_bounds__(NTHR, 1) lstm_main_kernel(
    const float* __restrict__ W_hh)    // [4H, H]
{
    float* sm_w  = smem;                 // [512 k][64 r]
    float* sm_hd = smem + SM_W;          // [512 k][32] (16 b duplicated)
    float* sm_r  = sm_hd + SM_HD;        // [4 kq][16 b][RPAD]
    float* sm_g  = sm_r + SM_R;          // [16 b][RPAD]

    const int tid = threadIdx.x;
    const int cta = blockIdx.x;
    const int g   = cta >> 5;            // group 0..3
    const int c   = cta & 31;            // cta within group

    // ---- one-time: W_hh slice, k-major ----
    for (int i = tid; i < 64 * 512; i += NTHR) {
        int r = i >> 9, k = i & 511;
        int n = (r >> 4) * Hn + c * 16 + (r & 15);
        sm_w[k * 64 + r] = W_hh[(size_t)n * Hn + k];
    }
    __syncthreads();

    // GEMM mapping: kq = k-quarter, npp = 4n-group, bq = 4b-group
    const int kq  = tid >> 6;
    const int tq  = tid & 63;
    const int npp = tq >> 2;             // 0..15
    const int bq  = tq & 3;              // 0..3
    const ulonglong2* wp = (const ulonglong2*)sm_w;   // 16B units
    const ulonglong2* hp = (const ulonglong2*)sm_hd;

    // epilogue mapping: tid = hl*16 + bl
    const int bl = tid & 15, hl = tid >> 4;
    float c_reg = 0.f;

    const unsigned* flags = g_flags + g * GC;

    for (int t = 0; t < Tn; ++t) {
        // ---- prefetch xproj for this step (independent of barrier) ----
        size_t xpb = (((size_t)t * NG + g) * GC + c) * 1024 + tid;
        float xp0 = __ldcg(g_xp + xpb);
        float xp1 = __ldcg(g_xp + xpb + 256);
        float xp2 = __ldcg(g_xp + xpb + 512);
        float xp3 = __ldcg(g_xp + xpb + 768);

        group_wait(flags, (unsigned)t, tid);

        // ---- stage h_t (32 KB = 2048 float4) duplicated into SMEM ----
        {
            const float4* src =
                (const float4*)(g_hist + ((size_t)t * NG + g) * Hn * BG);
            #pragma unroll
            for (int i = 0; i < 8; ++i) {               // 8*256 = 2048 float4
                int idx = tid + i * NTHR;
                float4 v = __ldcg(src + idx);
                int k = idx >> 2, q = idx & 3;
                float4* d0 = (float4*)(sm_hd + k * 32 + q * 8);
                d0[0] = make_float4(v.x, v.x, v.y, v.y);
                d0[1] = make_float4(v.z, v.z, v.w, v.w);
            }
        }
        __syncthreads();

        // ---- GEMM quarter-K: acc (4n x 4b) as 8 f32x2 (n-pair packed) ----
        unsigned long long a0 = 0, a1 = 0, a2 = 0, a3 = 0;
        unsigned long long a4 = 0, a5 = 0, a6 = 0, a7 = 0;
        const int kbase = kq * 128;
        #pragma unroll 4
        for (int kk = 0; kk < 128; ++kk) {
            int k = kbase + kk;
            ulonglong2 w2 = wp[k * 16 + npp];
            ulonglong2 h0 = hp[k * 8 + bq * 2];
            ulonglong2 h1 = hp[k * 8 + bq * 2 + 1];
            asm("fma.rn.f32x2 %0, %1, %2, %0;" : "+l"(a0) : "l"(w2.x), "l"(h0.x));
            asm("fma.rn.f32x2 %0, %1, %2, %0;" : "+l"(a1) : "l"(w2.x), "l"(h0.y));
            asm("fma.rn.f32x2 %0, %1, %2, %0;" : "+l"(a2) : "l"(w2.x), "l"(h1.x));
            asm("fma.rn.f32x2 %0, %1, %2, %0;" : "+l"(a3) : "l"(w2.x), "l"(h1.y));
            asm("fma.rn.f32x2 %0, %1, %2, %0;" : "+l"(a4) : "l"(w2.y), "l"(h0.x));
            asm("fma.rn.f32x2 %0, %1, %2, %0;" : "+l"(a5) : "l"(w2.y), "l"(h0.y));
            asm("fma.rn.f32x2 %0, %1, %2, %0;" : "+l"(a6) : "l"(w2.y), "l"(h1.x));
            asm("fma.rn.f32x2 %0, %1, %2, %0;" : "+l"(a7) : "l"(w2.y), "l"(h1.y));
        }

        // ---- store partials [kq][b][r] ----
        {
            float2 p0 = *(float2*)&a0, p4 = *(float2*)&a4;
            float2 p1 = *(float2*)&a1, p5 = *(float2*)&a5;
            float2 p2 = *(float2*)&a2, p6 = *(float2*)&a6;
            float2 p3 = *(float2*)&a3, p7 = *(float2*)&a7;
            float* base = sm_r + (kq * 16 + bq * 4) * RPAD + npp * 4;
            *(float4*)(base + 0 * RPAD) = make_float4(p0.x, p0.y, p4.x, p4.y);
            *(float4*)(base + 1 * RPAD) = make_float4(p1.x, p1.y, p5.x, p5.y);
            *(float4*)(base + 2 * RPAD) = make_float4(p2.x, p2.y, p6.x, p6.y);
            *(float4*)(base + 3 * RPAD) = make_float4(p3.x, p3.y, p7.x, p7.y);
        }
        __syncthreads();

        // ---- reduce 4 k-quarters -> sm_g[b][r] ----
        {
            int b = tid >> 4, nq = tid & 15;
            const float* rb = sm_r + b * RPAD + nq * 4;
            float4 s0 = *(const float4*)(rb);
            float4 s1 = *(const float4*)(rb + 16 * RPAD);
            float4 s2 = *(const float4*)(rb + 32 * RPAD);
            float4 s3 = *(const float4*)(rb + 48 * RPAD);
            float4 s = make_float4(s0.x + s1.x + s2.x + s3.x,
                                   s0.y + s1.y + s2.y + s3.y,
                                   s0.z + s1.z + s2.z + s3.z,
                                   s0.w + s1.w + s2.w + s3.w);
            *(float4*)(sm_g + b * RPAD + nq * 4) = s;
        }
        __syncthreads();

        // ---- LSTM cell epilogue ----
        {
            float xi = sm_g[bl * RPAD +  0 + hl] + xp0;
            float xf = sm_g[bl * RPAD + 16 + hl] + xp1;
            float xg = sm_g[bl * RPAD + 32 + hl] + xp2;
            float xo = sm_g[bl * RPAD + 48 + hl] + xp3;
            float ii = fsigmoid(xi);
            float ff = fsigmoid(xf);
            float gg = ftanh_(xg);
            float oo = fsigmoid(xo);
            c_reg = ff * c_reg + ii * gg;
            float h = oo * ftanh_(c_reg);
            g_hist[((size_t)(t + 1) * NG + g) * Hn * BG + c * 256 + tid] = h;
        }
        __syncthreads();

        // ---- publish per-CTA flag (release) ----
        if (tid == 0) {
            asm volatile("fence.acq_rel.gpu;" ::: "memory");
            asm volatile("st.volatile.global.u32 [%0], %1;"
                         :: "l"(&g_flags[cta]), "r"((unsigned)(t + 1)) : "memory");
        }
    }
}

// ---------------------------------------------------------------------------
// Conv1d(H,1,1): out[b][t] = sum_h hist[t+1][g(b)][h][bl(b)] * cw[h] + cb
// ---------------------------------------------------------------------------
__global__ void lstm_conv_kernel(const float* __restrict__ cw,
                                 const float* __restrict__ cb,
                                 float* __restrict__ out)
{
    __shared__ float scw[Hn];
    __shared__ float sred[NTHR];
    int t = blockIdx.x, tid = threadIdx.x;
    for (int i = tid; i < Hn; i += NTHR) scw[i] = cw[i];
    __syncthreads();
    int q = tid >> 6, b = tid & 63, g = b >> 4, bl = b & 15;
    const float* hp = g_hist + ((size_t)(t + 1) * NG + g) * Hn * BG + bl;
    float acc = 0.f;
    #pragma unroll 8
    for (int h = q * 128; h < q * 128 + 128; ++h)
        acc += __ldcg(hp + (size_t)h * BG) * scw[h];
    sred[tid] = acc;
    __syncthreads();
    if (q == 0)
        out[(size_t)b * Tn + t] =
            sred[b] + sred[b + 64] + sred[b + 128] + sred[b + 192] + cb[0];
}

// ---------------------------------------------------------------------------
extern "C" void kernel_launch(void* const* d_in, const int* in_sizes, int n_in,
                              void* d_out, int out_size)
{
    const float* x    = (const float*)d_in[0];  // (B, D, T)
    const float* W_ih = (const float*)d_in[1];  // (4H, D)
    const float* W_hh = (const float*)d_in[2];  // (4H, H)
    const float* b_ih = (const float*)d_in[3];  // (4H,)
    const float* b_hh = (const float*)d_in[4];  // (4H,)
    const float* cw   = (const float*)d_in[5];  // (1, H, 1)
    const float* cb   = (const float*)d_in[6];  // (1,)
    float* out = (float*)d_out;                 // (B, 1, T)

    cudaFuncSetAttribute(lstm_main_kernel,
                         cudaFuncAttributeMaxDynamicSharedMemorySize, SMEM_BYTES);

    lstm_prep_kernel<<<(Bn * Dn * Tn + 255) / 256, 256>>>(x);
    lstm_xproj_kernel<<<dim3(Tn, GC), NTHR>>>(W_ih, b_ih, b_hh);
    lstm_main_kernel<<<NCTA, NTHR, SMEM_BYTES>>>(W_hh);
    lstm_conv_kernel<<<Tn, NTHR>>>(cw, cb, out);
}